// round 3
// baseline (speedup 1.0000x reference)
#include <cuda_runtime.h>
#include <cuda_bf16.h>

#define S_GRID 14
#define INV_S (1.0f / 14.0f)
#define L_COORD 5.0f
#define L_NOOBJ 0.5f

// Accumulators: [0]=reg, [1]=contain, [2]=noobj, [3]=cls
// Zero-initialized at module load; the LAST block of each launch resets them
// to zero after consuming, so every graph replay sees a clean state.
__device__ float g_acc[4];
__device__ unsigned int g_block_count;

__device__ __forceinline__ float iou_vs_tgt(float x, float y, float w, float h,
                                            float tx1, float ty1, float tx2, float ty2,
                                            float ta) {
    float cx = x * INV_S;
    float cy = y * INV_S;
    float x1 = cx - 0.5f * w, y1 = cy - 0.5f * h;
    float x2 = cx + 0.5f * w, y2 = cy + 0.5f * h;
    float lx = fmaxf(x1, tx1), ly = fmaxf(y1, ty1);
    float rx = fminf(x2, tx2), ry = fminf(y2, ty2);
    float iw = fmaxf(rx - lx, 0.0f), ih = fmaxf(ry - ly, 0.0f);
    float inter = iw * ih;
    float a1 = (x2 - x1) * (y2 - y1);
    return inter / (a1 + ta - inter);
}

__global__ void __launch_bounds__(256) yolo_fused_kernel(
    const float* __restrict__ pred,            // [ncells, 30]
    const float* __restrict__ tbox,            // [ncells, 4]
    const float* __restrict__ tcls,            // [ncells, 20]
    const unsigned int* __restrict__ objmap,   // [ncells] bool widened to 4B (int32/f32)
    float* __restrict__ out,
    int ncells, float inv_n) {

    int i = blockIdx.x * blockDim.x + threadIdx.x;

    float reg = 0.0f, contain = 0.0f, noobj = 0.0f, cls = 0.0f;

    if (i < ncells) {
        const float* p = pred + (size_t)i * 30;
        bool has_obj = objmap[i] != 0u;   // nonzero for int32 1 and f32 1.0

        if (!has_obj) {
            float c1 = __ldg(p + 4);
            float c2 = __ldg(p + 9);
            noobj = L_NOOBJ * (c1 * c1 + c2 * c2);
        } else {
            float pv[30];
            #pragma unroll
            for (int j = 0; j < 15; j++) {
                float2 v = *reinterpret_cast<const float2*>(p + 2 * j);
                pv[2 * j]     = v.x;
                pv[2 * j + 1] = v.y;
            }
            float4 tb = *reinterpret_cast<const float4*>(tbox + (size_t)i * 4);

            const float* tc = tcls + (size_t)i * 20;
            float csum = 0.0f;
            #pragma unroll
            for (int j = 0; j < 5; j++) {
                float4 t = *reinterpret_cast<const float4*>(tc + 4 * j);
                float d0 = pv[10 + 4 * j + 0] - t.x;
                float d1 = pv[10 + 4 * j + 1] - t.y;
                float d2 = pv[10 + 4 * j + 2] - t.z;
                float d3 = pv[10 + 4 * j + 3] - t.w;
                csum += d0 * d0 + d1 * d1 + d2 * d2 + d3 * d3;
            }
            cls = csum;

            float tcx = tb.x * INV_S, tcy = tb.y * INV_S;
            float tx1 = tcx - 0.5f * tb.z, ty1 = tcy - 0.5f * tb.w;
            float tx2 = tcx + 0.5f * tb.z, ty2 = tcy + 0.5f * tb.w;
            float ta = (tx2 - tx1) * (ty2 - ty1);

            float iou1 = iou_vs_tgt(pv[0], pv[1], pv[2], pv[3], tx1, ty1, tx2, ty2, ta);
            float iou2 = iou_vs_tgt(pv[5], pv[6], pv[7], pv[8], tx1, ty1, tx2, ty2, ta);

            bool take1 = iou1 > iou2;
            float best_iou = take1 ? iou1 : iou2;
            float bx = take1 ? pv[0] : pv[5];
            float by = take1 ? pv[1] : pv[6];
            float bw = take1 ? pv[2] : pv[7];
            float bh = take1 ? pv[3] : pv[8];
            float bc = take1 ? pv[4] : pv[9];

            float dx = bx - tb.x, dy = by - tb.y;
            float xy_err = dx * dx + dy * dy;
            float dw = sqrtf(bw) - sqrtf(tb.z);
            float dh = sqrtf(bh) - sqrtf(tb.w);
            float wh_err = dw * dw + dh * dh;
            reg = L_COORD * (xy_err + wh_err);

            float dc = bc - best_iou;
            contain = dc * dc;
        }
    }

    // Warp reduce 4 components
    #pragma unroll
    for (int off = 16; off > 0; off >>= 1) {
        reg     += __shfl_down_sync(0xFFFFFFFFu, reg, off);
        contain += __shfl_down_sync(0xFFFFFFFFu, contain, off);
        noobj   += __shfl_down_sync(0xFFFFFFFFu, noobj, off);
        cls     += __shfl_down_sync(0xFFFFFFFFu, cls, off);
    }

    __shared__ float s_red[8][4];
    __shared__ bool s_is_last;
    int lane = threadIdx.x & 31;
    int warp = threadIdx.x >> 5;
    if (lane == 0) {
        s_red[warp][0] = reg;
        s_red[warp][1] = contain;
        s_red[warp][2] = noobj;
        s_red[warp][3] = cls;
    }
    __syncthreads();

    if (warp == 0) {
        // 4 components x 8 warps = 32 lanes
        int comp = lane >> 3;     // 0..3
        int w    = lane & 7;      // 0..7
        float v = s_red[w][comp];
        v += __shfl_down_sync(0xFFFFFFFFu, v, 4);
        v += __shfl_down_sync(0xFFFFFFFFu, v, 2);
        v += __shfl_down_sync(0xFFFFFFFFu, v, 1);
        if (w == 0) atomicAdd(&g_acc[comp], v);
        __syncwarp();
        if (lane == 0) {
            // Make our atomics visible, then count this block done.
            __threadfence();
            unsigned int done = atomicAdd(&g_block_count, 1u);
            s_is_last = (done == gridDim.x - 1);
        }
    }
    __syncthreads();

    // Last block finalizes: read totals, write output, reset state for next replay.
    if (s_is_last && threadIdx.x == 0) {
        float r  = g_acc[0];
        float ct = g_acc[1];
        float no = g_acc[2];
        float cl = g_acc[3];
        float total = r + ct + no + cl;
        out[0] = total * inv_n;
        out[1] = r  * inv_n;
        out[2] = ct * inv_n;
        out[3] = no * inv_n;
        out[4] = cl * inv_n;
        g_acc[0] = 0.0f; g_acc[1] = 0.0f; g_acc[2] = 0.0f; g_acc[3] = 0.0f;
        g_block_count = 0u;
        __threadfence();
    }
}

extern "C" void kernel_launch(void* const* d_in, const int* in_sizes, int n_in,
                              void* d_out, int out_size) {
    const float* pred = (const float*)d_in[0];
    const float* tbox = (const float*)d_in[1];
    const float* tcls = (const float*)d_in[2];
    const unsigned int* objmap = (const unsigned int*)d_in[3];

    int ncells = in_sizes[1] / 4;             // target_boxes has 4 per cell
    int n_imgs = ncells / (S_GRID * S_GRID);  // 4096

    int threads = 256;
    int blocks = (ncells + threads - 1) / threads;
    yolo_fused_kernel<<<blocks, threads>>>(pred, tbox, tcls, objmap,
                                           (float*)d_out, ncells,
                                           1.0f / (float)n_imgs);
}

// round 4
// speedup vs baseline: 1.1605x; 1.1605x over previous
#include <cuda_runtime.h>
#include <cuda_bf16.h>

#define S_GRID 14
#define INV_S (1.0f / 14.0f)
#define L_COORD 5.0f
#define L_NOOBJ 0.5f
#define CPT 4   // cells per thread

// Accumulators: [0]=reg, [1]=contain, [2]=noobj, [3]=cls
__device__ float g_acc[4];
__device__ unsigned int g_block_count;

__device__ __forceinline__ float iou_vs_tgt(float x, float y, float w, float h,
                                            float tx1, float ty1, float tx2, float ty2,
                                            float ta) {
    float cx = x * INV_S;
    float cy = y * INV_S;
    float x1 = cx - 0.5f * w, y1 = cy - 0.5f * h;
    float x2 = cx + 0.5f * w, y2 = cy + 0.5f * h;
    float lx = fmaxf(x1, tx1), ly = fmaxf(y1, ty1);
    float rx = fminf(x2, tx2), ry = fminf(y2, ty2);
    float iw = fmaxf(rx - lx, 0.0f), ih = fmaxf(ry - ly, 0.0f);
    float inter = iw * ih;
    float a1 = (x2 - x1) * (y2 - y1);
    return inter / (a1 + ta - inter);
}

// Full processing for one object cell (15% of cells).
__device__ __forceinline__ void process_obj_cell(
    const float* __restrict__ pred,
    const float* __restrict__ tbox,
    const float* __restrict__ tcls,
    int i, float& reg, float& contain, float& cls) {

    const float* p = pred + (size_t)i * 30;
    float pv[30];
    #pragma unroll
    for (int j = 0; j < 15; j++) {
        float2 v = *reinterpret_cast<const float2*>(p + 2 * j);
        pv[2 * j]     = v.x;
        pv[2 * j + 1] = v.y;
    }
    float4 tb = *reinterpret_cast<const float4*>(tbox + (size_t)i * 4);

    const float* tc = tcls + (size_t)i * 20;
    float csum = 0.0f;
    #pragma unroll
    for (int j = 0; j < 5; j++) {
        float4 t = *reinterpret_cast<const float4*>(tc + 4 * j);
        float d0 = pv[10 + 4 * j + 0] - t.x;
        float d1 = pv[10 + 4 * j + 1] - t.y;
        float d2 = pv[10 + 4 * j + 2] - t.z;
        float d3 = pv[10 + 4 * j + 3] - t.w;
        csum += d0 * d0 + d1 * d1 + d2 * d2 + d3 * d3;
    }
    cls += csum;

    float tcx = tb.x * INV_S, tcy = tb.y * INV_S;
    float tx1 = tcx - 0.5f * tb.z, ty1 = tcy - 0.5f * tb.w;
    float tx2 = tcx + 0.5f * tb.z, ty2 = tcy + 0.5f * tb.w;
    float ta = (tx2 - tx1) * (ty2 - ty1);

    float iou1 = iou_vs_tgt(pv[0], pv[1], pv[2], pv[3], tx1, ty1, tx2, ty2, ta);
    float iou2 = iou_vs_tgt(pv[5], pv[6], pv[7], pv[8], tx1, ty1, tx2, ty2, ta);

    bool take1 = iou1 > iou2;
    float best_iou = take1 ? iou1 : iou2;
    float bx = take1 ? pv[0] : pv[5];
    float by = take1 ? pv[1] : pv[6];
    float bw = take1 ? pv[2] : pv[7];
    float bh = take1 ? pv[3] : pv[8];
    float bc = take1 ? pv[4] : pv[9];

    float dx = bx - tb.x, dy = by - tb.y;
    float xy_err = dx * dx + dy * dy;
    float dw = sqrtf(bw) - sqrtf(tb.z);
    float dh = sqrtf(bh) - sqrtf(tb.w);
    float wh_err = dw * dw + dh * dh;
    reg += L_COORD * (xy_err + wh_err);

    float dc = bc - best_iou;
    contain += dc * dc;
}

__global__ void __launch_bounds__(256) yolo_fused_kernel(
    const float* __restrict__ pred,            // [ncells, 30]
    const float* __restrict__ tbox,            // [ncells, 4]
    const float* __restrict__ tcls,            // [ncells, 20]
    const uint4* __restrict__ objmap4,         // [ncells/4] bool widened to 4B, read as uint4
    float* __restrict__ out,
    int ncells, float inv_n) {

    int t = blockIdx.x * blockDim.x + threadIdx.x;
    int c0 = t * CPT;

    float reg = 0.0f, contain = 0.0f, noobj = 0.0f, cls = 0.0f;

    if (c0 < ncells) {
        // ---- Phase 1: all independent loads issued up front (max MLP) ----
        uint4 om = objmap4[t];   // 4 flags, coalesced 16B

        const float* p0 = pred + (size_t)c0 * 30;
        float cf[2 * CPT];
        #pragma unroll
        for (int k = 0; k < CPT; k++) {
            cf[2 * k]     = __ldg(p0 + k * 30 + 4);
            cf[2 * k + 1] = __ldg(p0 + k * 30 + 9);
        }

        unsigned int flags[CPT] = {om.x, om.y, om.z, om.w};

        // ---- Phase 2: cheap no-obj contributions (common case, no more loads) ----
        #pragma unroll
        for (int k = 0; k < CPT; k++) {
            if (flags[k] == 0u) {
                float c1 = cf[2 * k], c2 = cf[2 * k + 1];
                noobj += L_NOOBJ * (c1 * c1 + c2 * c2);
            }
        }

        // ---- Phase 3: rare full obj-cell processing ----
        #pragma unroll
        for (int k = 0; k < CPT; k++) {
            if (flags[k] != 0u) {
                process_obj_cell(pred, tbox, tcls, c0 + k, reg, contain, cls);
            }
        }
    }

    // Warp reduce 4 components
    #pragma unroll
    for (int off = 16; off > 0; off >>= 1) {
        reg     += __shfl_down_sync(0xFFFFFFFFu, reg, off);
        contain += __shfl_down_sync(0xFFFFFFFFu, contain, off);
        noobj   += __shfl_down_sync(0xFFFFFFFFu, noobj, off);
        cls     += __shfl_down_sync(0xFFFFFFFFu, cls, off);
    }

    __shared__ float s_red[8][4];
    __shared__ bool s_is_last;
    int lane = threadIdx.x & 31;
    int warp = threadIdx.x >> 5;
    if (lane == 0) {
        s_red[warp][0] = reg;
        s_red[warp][1] = contain;
        s_red[warp][2] = noobj;
        s_red[warp][3] = cls;
    }
    __syncthreads();

    if (warp == 0) {
        int comp = lane >> 3;     // 0..3
        int w    = lane & 7;      // 0..7
        float v = s_red[w][comp];
        v += __shfl_down_sync(0xFFFFFFFFu, v, 4);
        v += __shfl_down_sync(0xFFFFFFFFu, v, 2);
        v += __shfl_down_sync(0xFFFFFFFFu, v, 1);
        if (w == 0) atomicAdd(&g_acc[comp], v);
        __syncwarp();
        if (lane == 0) {
            __threadfence();
            unsigned int done = atomicAdd(&g_block_count, 1u);
            s_is_last = (done == gridDim.x - 1);
        }
    }
    __syncthreads();

    if (s_is_last && threadIdx.x == 0) {
        float r  = g_acc[0];
        float ct = g_acc[1];
        float no = g_acc[2];
        float cl = g_acc[3];
        float total = r + ct + no + cl;
        out[0] = total * inv_n;
        out[1] = r  * inv_n;
        out[2] = ct * inv_n;
        out[3] = no * inv_n;
        out[4] = cl * inv_n;
        g_acc[0] = 0.0f; g_acc[1] = 0.0f; g_acc[2] = 0.0f; g_acc[3] = 0.0f;
        g_block_count = 0u;
        __threadfence();
    }
}

extern "C" void kernel_launch(void* const* d_in, const int* in_sizes, int n_in,
                              void* d_out, int out_size) {
    const float* pred = (const float*)d_in[0];
    const float* tbox = (const float*)d_in[1];
    const float* tcls = (const float*)d_in[2];
    const uint4* objmap4 = (const uint4*)d_in[3];

    int ncells = in_sizes[1] / 4;             // target_boxes has 4 per cell
    int n_imgs = ncells / (S_GRID * S_GRID);  // 4096

    int threads = 256;
    int nthreads_total = (ncells + CPT - 1) / CPT;   // 200704, exact for 4096*196
    int blocks = (nthreads_total + threads - 1) / threads;   // 784
    yolo_fused_kernel<<<blocks, threads>>>(pred, tbox, tcls, objmap4,
                                           (float*)d_out, ncells,
                                           1.0f / (float)n_imgs);
}